// round 14
// baseline (speedup 1.0000x reference)
#include <cuda_runtime.h>
#include <cuda_fp16.h>
#include <cstdint>

// ---------------------------------------------------------------------------
// NodeUnpool via fp16 HMMA (m16n8k16.f16, fp32 accumulate), single product,
// bulk row-copy interleaved into the GEMM CTA:
//   out = h_full;  out[idx] = h_full[idx]@W1^T + b1 + h_sub@W2^T + b2
// C[M,256] = [h_full[idx] | h_sub] @ [W1 | W2]^T   (K = 512 concat)
//
// R14: R13 content (inline dtype detect, hoisted copy loads) with the graph
// capture fork FIXED: all side-stream work is forked from stream 0 via an
// event before any launch on the side stream (R12-proven topology).
// ---------------------------------------------------------------------------

#define DIM      256
#define BM       128
#define BN       256
#define KC       64
#define THREADS  512
#define ROWB     144            // 64 halves = 128B + 16B pad (conflict-free)

// smem layout (bytes)
#define SM_ROWIDX 0             // int[128]
#define SM_BIAS   512           // float[256]
#define SM_MASK   1536          // uchar[1024] copy-slice masks
#define A_STAGE   (128 * ROWB)  // 18432
#define B_STAGE   (256 * ROWB)  // 36864
#define SM_A      2560          // 2 stages
#define SM_B      (SM_A + 2 * A_STAGE)      // 39424
#define SM_TOTAL  (SM_B + 2 * B_STAGE)      // 113152

#define MASK_CAP  (2u << 20)

__device__ int g_idx_is64;
__device__ __align__(16) __half g_Bw[256 * 512];          // [n][kcat] fp16
__device__ __align__(16) unsigned char g_mask[MASK_CAP];  // 1 = pooled row

// ---------------- helpers ----------------
__device__ __forceinline__ uint32_t smem_u32(const void* p) {
    uint32_t a;
    asm("{ .reg .u64 t; cvta.to.shared.u64 t, %1; cvt.u32.u64 %0, t; }"
        : "=r"(a) : "l"(p));
    return a;
}
__device__ __forceinline__ void cp_async16(uint32_t dst, const void* src) {
    asm volatile("cp.async.cg.shared.global [%0], [%1], 16;"
                 :: "r"(dst), "l"(src) : "memory");
}
__device__ __forceinline__ void cp_commit() {
    asm volatile("cp.async.commit_group;" ::: "memory");
}
__device__ __forceinline__ void cp_wait0() {
    asm volatile("cp.async.wait_group 0;" ::: "memory");
}
__device__ __forceinline__ void ldsm4(uint32_t* r, uint32_t addr) {
    asm volatile("ldmatrix.sync.aligned.m8n8.x4.shared.b16 {%0,%1,%2,%3}, [%4];"
                 : "=r"(r[0]), "=r"(r[1]), "=r"(r[2]), "=r"(r[3]) : "r"(addr));
}
__device__ __forceinline__ uint32_t lds32(uint32_t addr) {
    uint32_t v;
    asm volatile("ld.shared.b32 %0, [%1];" : "=r"(v) : "r"(addr));
    return v;
}
__device__ __forceinline__ void hmma(float* d, const uint32_t* a,
                                     uint32_t b0, uint32_t b1) {
    asm volatile(
        "mma.sync.aligned.m16n8k16.row.col.f32.f16.f16.f32 "
        "{%0,%1,%2,%3}, {%4,%5,%6,%7}, {%8,%9}, {%0,%1,%2,%3};"
        : "+f"(d[0]), "+f"(d[1]), "+f"(d[2]), "+f"(d[3])
        : "r"(a[0]), "r"(a[1]), "r"(a[2]), "r"(a[3]), "r"(b0), "r"(b1));
}

// ---------------- idx dtype ----------------
__device__ __forceinline__ long long load_idx(const void* idx, int r, int is64) {
    if (is64) return reinterpret_cast<const long long*>(idx)[r];
    return (long long)reinterpret_cast<const int*>(idx)[r];
}

// ---------------- mask clear (+ inline dtype detection) ----------------
__global__ void clear_mask(int nWords, const void* idx, int Mrows,
                           long long Nfull) {
    int t = blockIdx.x * blockDim.x + threadIdx.x;
    uint4* p = reinterpret_cast<uint4*>(g_mask);
    if (t < nWords) p[t] = make_uint4(0, 0, 0, 0);
    if (t == 0) {
        const long long* p64 = reinterpret_cast<const long long*>(idx);
        int n = Mrows / 2;
        if (n > 8) n = 8;
        bool ok64 = (n > 0);
        for (int i = 0; i < n; ++i) {
            long long v = p64[i];
            if (v < 0 || v >= Nfull) { ok64 = false; break; }
        }
        g_idx_is64 = ok64 ? 1 : 0;
    }
}
__global__ void set_mask(const void* __restrict__ idx, int Mrows) {
    int t = blockIdx.x * blockDim.x + threadIdx.x;
    if (t < Mrows) {
        long long g = load_idx(idx, t, g_idx_is64);
        g_mask[g] = 1;
    }
}

// ---------------- W -> fp16, [n][kcat] ----------------
__global__ void convert_W(const float* __restrict__ W1, const float* __restrict__ W2) {
    int t = blockIdx.x * blockDim.x + threadIdx.x;   // 256*512
    if (t >= 256 * 512) return;
    int n    = t >> 9;
    int kcat = t & 511;
    float x = (kcat < DIM) ? W1[n * DIM + kcat] : W2[n * DIM + (kcat - DIM)];
    g_Bw[t] = __float2half_rn(x);
}

// ---------------- fused GEMM + interleaved masked copy ----------------
__global__ __launch_bounds__(THREADS, 1)
void merge_gemm_fp16(const float* __restrict__ h_full,
                     const float* __restrict__ h_sub,
                     const float* __restrict__ b1,
                     const float* __restrict__ b2,
                     const void*  __restrict__ idx,
                     float* __restrict__ out,
                     int Mrows, int Nfull, int rowsPer)
{
    extern __shared__ __align__(16) char smem[];
    const uint32_t sbase = smem_u32(smem);

    const int tid   = threadIdx.x;
    const int wid   = tid >> 5;
    const int lid   = tid & 31;
    const int tileM = blockIdx.x * BM;
    const int warpM = (wid & 3) * 32;      // 4 warps in M
    const int warpN = (wid >> 2) * 64;     // 4 warp groups in N

    int*           rowidx = (int*)(smem + SM_ROWIDX);
    float*         biasS  = (float*)(smem + SM_BIAS);
    unsigned char* maskS  = (unsigned char*)(smem + SM_MASK);

    // ---- copy slice for this CTA
    const int rows0   = blockIdx.x * rowsPer;
    const int rcChunk = min(64, (rowsPer + 7) / 8);   // rows per K-chunk
    const int halfR   = (rcChunk + 1) / 2;            // rows per group (<=32)

    const int is64 = g_idx_is64;
    if (tid < BM) {
        int m = tileM + tid;
        rowidx[tid] = (m < Mrows) ? (int)load_idx(idx, m, is64) : 0;
    }
    if (tid < DIM) biasS[tid] = b1[tid] + b2[tid];
    // stage copy-slice masks (<=1024 rows)
    {
        int rl = tid;                                  // 0..511
        int r0 = rows0 + rl;
        maskS[rl] = (rl < rowsPer && r0 < Nfull) ? g_mask[r0] : 1;
        rl += THREADS;
        r0 += THREADS;
        if (rl < 1024) maskS[rl] = (rl < rowsPer && r0 < Nfull) ? g_mask[r0] : 1;
    }
    __syncthreads();

    // ---- B stage fill via cp.async: 256 rows x 128B -> 2048 x 16B segs
    auto issueB = [&](int c, int st) {
        uint32_t dbase = sbase + SM_B + st * B_STAGE;
#pragma unroll
        for (int j = 0; j < 4; ++j) {
            int id  = tid + j * THREADS;     // 0..2047
            int row = id >> 3;               // 0..255
            int seg = id & 7;                // 16B segment
            uint32_t dst = dbase + row * ROWB + seg * 16;
            const char* src = (const char*)g_Bw
                            + (((size_t)row << 9) + c * KC + seg * 8) * 2;
            cp_async16(dst, src);
        }
    };

    // ---- A chunk gather into regs: 2048 float4, 4 per thread
    auto loadA = [&](float4* dst, int c) {
        const bool fromFull = (c < 4);
        const int  kb = (c & 3) * KC;
#pragma unroll
        for (int j = 0; j < 4; ++j) {
            int id = tid + j * THREADS;      // 0..2047
            int r  = id >> 4;                // 0..127
            int c4 = (id & 15) << 2;         // 0..60
            const float* src;
            if (fromFull) {
                src = h_full + (size_t)rowidx[r] * DIM;
            } else {
                int m = tileM + r;
                if (m >= Mrows) m = Mrows - 1;
                src = h_sub + (size_t)m * DIM;
            }
            dst[j] = __ldcs((const float4*)(src + kb + c4));
        }
    };

    // ---- A regs -> fp16 smem (stage st)
    auto storeA = [&](const float4* v, int st) {
        uint32_t abase = (uint32_t)(SM_A + st * A_STAGE);
#pragma unroll
        for (int j = 0; j < 4; ++j) {
            int id = tid + j * THREADS;
            int r  = id >> 4;
            int c4 = (id & 15) << 2;
            float4 q = v[j];
            __half2 p01 = __floats2half2_rn(q.x, q.y);
            __half2 p23 = __floats2half2_rn(q.z, q.w);
            *(uint2*)(smem + abase + r * ROWB + c4 * 2) =
                make_uint2(*(uint32_t*)&p01, *(uint32_t*)&p23);
        }
    };

    float acc[2][8][4];
#pragma unroll
    for (int mt = 0; mt < 2; ++mt)
#pragma unroll
        for (int nt = 0; nt < 8; ++nt)
#pragma unroll
            for (int q = 0; q < 4; ++q) acc[mt][nt][q] = 0.f;

    // ---- compute HALF a KC chunk (kk pair) from stage st
    auto computeH = [&](int st, int kh) {
        const uint32_t aB = sbase + SM_A + st * A_STAGE;
        const uint32_t bB = sbase + SM_B + st * B_STAGE;
#pragma unroll
        for (int kk = kh * 2; kk < kh * 2 + 2; ++kk) {
            uint32_t a[2][4];
#pragma unroll
            for (int mt = 0; mt < 2; ++mt) {
                uint32_t ra = (uint32_t)(warpM + mt * 16 + (lid & 15)) * ROWB
                            + (kk * 16 + (lid >> 4) * 8) * 2;
                ldsm4(a[mt], aB + ra);
            }
#pragma unroll
            for (int nt = 0; nt < 8; ++nt) {
                uint32_t rb = bB + (uint32_t)(warpN + nt * 8 + (lid >> 2)) * ROWB
                            + (kk * 16 + (lid & 3) * 2) * 2;
                uint32_t b0 = lds32(rb), b1v = lds32(rb + 16);
#pragma unroll
                for (int mt = 0; mt < 2; ++mt)
                    hmma(acc[mt][nt], a[mt], b0, b1v);
            }
        }
    };

    // ---- interleaved copy machinery: 1 row / thread-group-of-16 per group
    const float4* in4  = reinterpret_cast<const float4*>(h_full);
    float4*       out4 = reinterpret_cast<float4*>(out);
    const int cRowT = tid >> 4;          // 0..31
    const int cColT = tid & 15;          // f4 lane: cols cColT + i*16

    float4 cb[4];
    int  cRowG  = -1;
    bool cActive = false;

    auto copyLoad = [&](int c, int g) {
        int rl = c * rcChunk + g * halfR + cRowT;       // local row
        int rg = rows0 + rl;
        cActive = (cRowT < halfR) && (rl < rowsPer) && (rg < Nfull)
                  && (maskS[rl] == 0);
        cRowG = rg;
        if (cActive) {
            size_t base = ((size_t)rg << 6) + cColT;
#pragma unroll
            for (int i = 0; i < 4; ++i)
                cb[i] = __ldcs(&in4[base + i * 16]);
        }
    };
    auto copyStore = [&]() {
        if (cActive) {
            size_t base = ((size_t)cRowG << 6) + cColT;
#pragma unroll
            for (int i = 0; i < 4; ++i)
                __stcs(&out4[base + i * 16], cb[i]);
        }
    };

    // ---- prologue: chunk 0 into stage 0
    float4 aPre[4];
    issueB(0, 0);
    cp_commit();
    loadA(aPre, 0);
    storeA(aPre, 0);
    cp_wait0();
    __syncthreads();

    // ---- main loop: GEMM chunks with interleaved copy groups
#pragma unroll 1
    for (int c = 0; c < 8; ++c) {
        const int st = c & 1;
        copyLoad(c, 0);          // earliest: hides under gather + computeH0
        if (c < 7) {
            issueB(c + 1, st ^ 1);
            cp_commit();
            loadA(aPre, c + 1);
        }
        computeH(st, 0);
        copyStore();
        copyLoad(c, 1);          // loads covered by computeH(...,1)
        computeH(st, 1);
        copyStore();
        if (c < 7) {
            storeA(aPre, st ^ 1);
            cp_wait0();
        }
        __syncthreads();
    }

    // ---- tail copy rows (if rowsPer > 8*rcChunk; none for default shape)
    for (int rl = 8 * rcChunk + cRowT; rl < rowsPer; rl += 32) {
        int rg = rows0 + rl;
        if (rg < Nfull) {
            bool cp = (rl < 1024) ? (maskS[rl] == 0) : (g_mask[rg] == 0);
            if (cp) {
                size_t base = ((size_t)rg << 6) + cColT;
#pragma unroll
                for (int i = 0; i < 4; ++i)
                    __stcs(&out4[base + i * 16], __ldcs(&in4[base + i * 16]));
            }
        }
    }

    // ---- epilogue: bias add + scatter (streaming stores)
    {
        const int r0 = lid >> 2;
        const int nc = (lid & 3) * 2;
#pragma unroll
        for (int mt = 0; mt < 2; ++mt) {
#pragma unroll
            for (int half = 0; half < 2; ++half) {
                int row = warpM + mt * 16 + r0 + half * 8;
                int mg  = tileM + row;
                if (mg < Mrows) {
                    float* orow = out + (size_t)rowidx[row] * DIM + warpN;
#pragma unroll
                    for (int nt = 0; nt < 8; ++nt) {
                        float2 bv = *(const float2*)&biasS[warpN + nt * 8 + nc];
                        float2 v;
                        v.x = acc[mt][nt][half * 2 + 0] + bv.x;
                        v.y = acc[mt][nt][half * 2 + 1] + bv.y;
                        __stcs((float2*)(orow + nt * 8 + nc), v);
                    }
                }
            }
        }
    }
}

// ---------------- launch ----------------
extern "C" void kernel_launch(void* const* d_in, const int* in_sizes, int n_in,
                              void* d_out, int out_size) {
    const float* h_full = (const float*)d_in[0];
    const float* h_sub  = (const float*)d_in[1];
    const float* W1     = (const float*)d_in[2];
    const float* b1     = (const float*)d_in[3];
    const float* W2     = (const float*)d_in[4];
    const float* b2     = (const float*)d_in[5];
    const void*  idx    = d_in[6];
    float*       out    = (float*)d_out;

    const int dim   = in_sizes[3];
    const int Mrows = in_sizes[1] / dim;
    const int Nfull = in_sizes[0] / dim;

    static cudaStream_t sPrep = nullptr;
    static cudaEvent_t  evFork = nullptr, evMask = nullptr;
    if (!sPrep) {
        cudaStreamCreateWithFlags(&sPrep, cudaStreamNonBlocking);
        cudaEventCreateWithFlags(&evFork, cudaEventDisableTiming);
        cudaEventCreateWithFlags(&evMask, cudaEventDisableTiming);
    }

    cudaFuncSetAttribute(merge_gemm_fp16,
                         cudaFuncAttributeMaxDynamicSharedMemorySize, SM_TOTAL);

    // ---- fork side stream FROM stream 0 (capture-legal), prep in parallel
    cudaEventRecord(evFork, 0);
    cudaStreamWaitEvent(sPrep, evFork, 0);

    const int maskWords = (Nfull + 15) / 16;
    clear_mask<<<(maskWords + 255) / 256, 256, 0, sPrep>>>(
        maskWords, idx, Mrows, (long long)Nfull);
    set_mask<<<(Mrows + 255) / 256, 256, 0, sPrep>>>(idx, Mrows);
    cudaEventRecord(evMask, sPrep);

    convert_W<<<(256 * 512 + 255) / 256, 256>>>(W1, W2);
    cudaStreamWaitEvent(0, evMask, 0);

    // ---- fused GEMM + copy ----
    const int tiles   = (Mrows + BM - 1) / BM;
    const int rowsPer = (Nfull + tiles - 1) / tiles;
    merge_gemm_fp16<<<tiles, THREADS, SM_TOTAL>>>(h_full, h_sub, b1, b2, idx,
                                                  out, Mrows, Nfull, rowsPer);
}

// round 15
// speedup vs baseline: 1.1686x; 1.1686x over previous
#include <cuda_runtime.h>
#include <cuda_fp16.h>
#include <cstdint>

// ---------------------------------------------------------------------------
// NodeUnpool via fp16 HMMA (m16n8k16.f16, fp32 accumulate), single product,
// bulk row-copy interleaved into the GEMM CTA:
//   out = h_full;  out[idx] = h_full[idx]@W1^T + b1 + h_sub@W2^T + b2
// C[M,256] = [h_full[idx] | h_sub] @ [W1 | W2]^T   (K = 512 concat)
//
// R15: BM=64 / 256-thread CTAs -> 2 CTAs per SM (R14 profile showed the
// 512-thread/128-reg CTA monopolized the SM: occ 24.8%, DRAM 51%, tensor 31%
// -- latency-bound). Cross-CTA overlap hides barrier + pipeline stalls.
// Copy-load ordering reverted to the R12-proven schedule.
// ---------------------------------------------------------------------------

#define DIM      256
#define BM       64
#define BN       256
#define KC       64
#define THREADS  256
#define ROWB     144            // 64 halves = 128B + 16B pad (conflict-free)

// smem layout (bytes)
#define SM_ROWIDX 0             // int[64]
#define SM_BIAS   512           // float[256]
#define SM_MASK   1536          // uchar[512] copy-slice masks
#define A_STAGE   (64 * ROWB)   // 9216
#define B_STAGE   (256 * ROWB)  // 36864
#define SM_A      2048          // 2 stages
#define SM_B      (SM_A + 2 * A_STAGE)      // 20480
#define SM_TOTAL  (SM_B + 2 * B_STAGE)      // 94208

#define MASK_CAP  (2u << 20)

__device__ int g_idx_is64;
__device__ __align__(16) __half g_Bw[256 * 512];          // [n][kcat] fp16
__device__ __align__(16) unsigned char g_mask[MASK_CAP];  // 1 = pooled row

// ---------------- helpers ----------------
__device__ __forceinline__ uint32_t smem_u32(const void* p) {
    uint32_t a;
    asm("{ .reg .u64 t; cvta.to.shared.u64 t, %1; cvt.u32.u64 %0, t; }"
        : "=r"(a) : "l"(p));
    return a;
}
__device__ __forceinline__ void cp_async16(uint32_t dst, const void* src) {
    asm volatile("cp.async.cg.shared.global [%0], [%1], 16;"
                 :: "r"(dst), "l"(src) : "memory");
}
__device__ __forceinline__ void cp_commit() {
    asm volatile("cp.async.commit_group;" ::: "memory");
}
__device__ __forceinline__ void cp_wait0() {
    asm volatile("cp.async.wait_group 0;" ::: "memory");
}
__device__ __forceinline__ void ldsm4(uint32_t* r, uint32_t addr) {
    asm volatile("ldmatrix.sync.aligned.m8n8.x4.shared.b16 {%0,%1,%2,%3}, [%4];"
                 : "=r"(r[0]), "=r"(r[1]), "=r"(r[2]), "=r"(r[3]) : "r"(addr));
}
__device__ __forceinline__ uint32_t lds32(uint32_t addr) {
    uint32_t v;
    asm volatile("ld.shared.b32 %0, [%1];" : "=r"(v) : "r"(addr));
    return v;
}
__device__ __forceinline__ void hmma(float* d, const uint32_t* a,
                                     uint32_t b0, uint32_t b1) {
    asm volatile(
        "mma.sync.aligned.m16n8k16.row.col.f32.f16.f16.f32 "
        "{%0,%1,%2,%3}, {%4,%5,%6,%7}, {%8,%9}, {%0,%1,%2,%3};"
        : "+f"(d[0]), "+f"(d[1]), "+f"(d[2]), "+f"(d[3])
        : "r"(a[0]), "r"(a[1]), "r"(a[2]), "r"(a[3]), "r"(b0), "r"(b1));
}

// ---------------- idx dtype ----------------
__device__ __forceinline__ long long load_idx(const void* idx, int r, int is64) {
    if (is64) return reinterpret_cast<const long long*>(idx)[r];
    return (long long)reinterpret_cast<const int*>(idx)[r];
}

// ---------------- mask clear (+ inline dtype detection) ----------------
__global__ void clear_mask(int nWords, const void* idx, int Mrows,
                           long long Nfull) {
    int t = blockIdx.x * blockDim.x + threadIdx.x;
    uint4* p = reinterpret_cast<uint4*>(g_mask);
    if (t < nWords) p[t] = make_uint4(0, 0, 0, 0);
    if (t == 0) {
        const long long* p64 = reinterpret_cast<const long long*>(idx);
        int n = Mrows / 2;
        if (n > 8) n = 8;
        bool ok64 = (n > 0);
        for (int i = 0; i < n; ++i) {
            long long v = p64[i];
            if (v < 0 || v >= Nfull) { ok64 = false; break; }
        }
        g_idx_is64 = ok64 ? 1 : 0;
    }
}
__global__ void set_mask(const void* __restrict__ idx, int Mrows) {
    int t = blockIdx.x * blockDim.x + threadIdx.x;
    if (t < Mrows) {
        long long g = load_idx(idx, t, g_idx_is64);
        g_mask[g] = 1;
    }
}

// ---------------- W -> fp16, [n][kcat] ----------------
__global__ void convert_W(const float* __restrict__ W1, const float* __restrict__ W2) {
    int t = blockIdx.x * blockDim.x + threadIdx.x;   // 256*512
    if (t >= 256 * 512) return;
    int n    = t >> 9;
    int kcat = t & 511;
    float x = (kcat < DIM) ? W1[n * DIM + kcat] : W2[n * DIM + (kcat - DIM)];
    g_Bw[t] = __float2half_rn(x);
}

// ---------------- fused GEMM + interleaved masked copy ----------------
__global__ __launch_bounds__(THREADS, 2)
void merge_gemm_fp16(const float* __restrict__ h_full,
                     const float* __restrict__ h_sub,
                     const float* __restrict__ b1,
                     const float* __restrict__ b2,
                     const void*  __restrict__ idx,
                     float* __restrict__ out,
                     int Mrows, int Nfull, int rowsPer)
{
    extern __shared__ __align__(16) char smem[];
    const uint32_t sbase = smem_u32(smem);

    const int tid   = threadIdx.x;
    const int wid   = tid >> 5;
    const int lid   = tid & 31;
    const int tileM = blockIdx.x * BM;
    const int warpM = (wid & 1) * 32;      // 2 warps in M
    const int warpN = (wid >> 1) * 64;     // 4 warp groups in N

    int*           rowidx = (int*)(smem + SM_ROWIDX);
    float*         biasS  = (float*)(smem + SM_BIAS);
    unsigned char* maskS  = (unsigned char*)(smem + SM_MASK);

    // ---- copy slice for this CTA
    const int rows0   = blockIdx.x * rowsPer;
    const int rcChunk = min(32, (rowsPer + 7) / 8);   // rows per K-chunk
    const int halfR   = (rcChunk + 1) / 2;            // rows per group (<=16)

    const int is64 = g_idx_is64;
    if (tid < BM) {
        int m = tileM + tid;
        rowidx[tid] = (m < Mrows) ? (int)load_idx(idx, m, is64) : 0;
    }
    if (tid < DIM) biasS[tid] = b1[tid] + b2[tid];
    // stage copy-slice masks (<=512 rows)
    {
        int rl = tid;                                  // 0..255
        int r0 = rows0 + rl;
        maskS[rl] = (rl < rowsPer && r0 < Nfull) ? g_mask[r0] : 1;
        rl += THREADS;
        r0 += THREADS;
        if (rl < 512) maskS[rl] = (rl < rowsPer && r0 < Nfull) ? g_mask[r0] : 1;
    }
    __syncthreads();

    // ---- B stage fill via cp.async: 256 rows x 128B -> 2048 x 16B segs
    auto issueB = [&](int c, int st) {
        uint32_t dbase = sbase + SM_B + st * B_STAGE;
#pragma unroll
        for (int j = 0; j < 8; ++j) {
            int id  = tid + j * THREADS;     // 0..2047
            int row = id >> 3;               // 0..255
            int seg = id & 7;                // 16B segment
            uint32_t dst = dbase + row * ROWB + seg * 16;
            const char* src = (const char*)g_Bw
                            + (((size_t)row << 9) + c * KC + seg * 8) * 2;
            cp_async16(dst, src);
        }
    };

    // ---- A chunk gather into regs: 1024 float4, 4 per thread
    auto loadA = [&](float4* dst, int c) {
        const bool fromFull = (c < 4);
        const int  kb = (c & 3) * KC;
#pragma unroll
        for (int j = 0; j < 4; ++j) {
            int id = tid + j * THREADS;      // 0..1023
            int r  = id >> 4;                // 0..63
            int c4 = (id & 15) << 2;         // 0..60
            const float* src;
            if (fromFull) {
                src = h_full + (size_t)rowidx[r] * DIM;
            } else {
                int m = tileM + r;
                if (m >= Mrows) m = Mrows - 1;
                src = h_sub + (size_t)m * DIM;
            }
            dst[j] = __ldcs((const float4*)(src + kb + c4));
        }
    };

    // ---- A regs -> fp16 smem (stage st)
    auto storeA = [&](const float4* v, int st) {
        uint32_t abase = (uint32_t)(SM_A + st * A_STAGE);
#pragma unroll
        for (int j = 0; j < 4; ++j) {
            int id = tid + j * THREADS;
            int r  = id >> 4;
            int c4 = (id & 15) << 2;
            float4 q = v[j];
            __half2 p01 = __floats2half2_rn(q.x, q.y);
            __half2 p23 = __floats2half2_rn(q.z, q.w);
            *(uint2*)(smem + abase + r * ROWB + c4 * 2) =
                make_uint2(*(uint32_t*)&p01, *(uint32_t*)&p23);
        }
    };

    float acc[2][8][4];
#pragma unroll
    for (int mt = 0; mt < 2; ++mt)
#pragma unroll
        for (int nt = 0; nt < 8; ++nt)
#pragma unroll
            for (int q = 0; q < 4; ++q) acc[mt][nt][q] = 0.f;

    // ---- compute HALF a KC chunk (kk pair) from stage st
    auto computeH = [&](int st, int kh) {
        const uint32_t aB = sbase + SM_A + st * A_STAGE;
        const uint32_t bB = sbase + SM_B + st * B_STAGE;
#pragma unroll
        for (int kk = kh * 2; kk < kh * 2 + 2; ++kk) {
            uint32_t a[2][4];
#pragma unroll
            for (int mt = 0; mt < 2; ++mt) {
                uint32_t ra = (uint32_t)(warpM + mt * 16 + (lid & 15)) * ROWB
                            + (kk * 16 + (lid >> 4) * 8) * 2;
                ldsm4(a[mt], aB + ra);
            }
#pragma unroll
            for (int nt = 0; nt < 8; ++nt) {
                uint32_t rb = bB + (uint32_t)(warpN + nt * 8 + (lid >> 2)) * ROWB
                            + (kk * 16 + (lid & 3) * 2) * 2;
                uint32_t b0 = lds32(rb), b1v = lds32(rb + 16);
#pragma unroll
                for (int mt = 0; mt < 2; ++mt)
                    hmma(acc[mt][nt], a[mt], b0, b1v);
            }
        }
    };

    // ---- interleaved copy machinery: 1 row / thread-group-of-16 per group
    const float4* in4  = reinterpret_cast<const float4*>(h_full);
    float4*       out4 = reinterpret_cast<float4*>(out);
    const int cRowT = tid >> 4;          // 0..15
    const int cColT = tid & 15;          // f4 lane: cols cColT + i*16

    float4 cb[4];
    int  cRowG  = -1;
    bool cActive = false;

    auto copyLoad = [&](int c, int g) {
        int rl = c * rcChunk + g * halfR + cRowT;       // local row
        int rg = rows0 + rl;
        cActive = (cRowT < halfR) && (rl < rowsPer) && (rg < Nfull)
                  && (maskS[rl] == 0);
        cRowG = rg;
        if (cActive) {
            size_t base = ((size_t)rg << 6) + cColT;
#pragma unroll
            for (int i = 0; i < 4; ++i)
                cb[i] = __ldcs(&in4[base + i * 16]);
        }
    };
    auto copyStore = [&]() {
        if (cActive) {
            size_t base = ((size_t)cRowG << 6) + cColT;
#pragma unroll
            for (int i = 0; i < 4; ++i)
                __stcs(&out4[base + i * 16], cb[i]);
        }
    };

    // ---- prologue: chunk 0 into stage 0
    float4 aPre[4];
    issueB(0, 0);
    cp_commit();
    loadA(aPre, 0);
    storeA(aPre, 0);
    cp_wait0();
    __syncthreads();

    // ---- main loop: GEMM chunks with interleaved copy groups (R12 order)
#pragma unroll 1
    for (int c = 0; c < 8; ++c) {
        const int st = c & 1;
        if (c < 7) {
            issueB(c + 1, st ^ 1);
            cp_commit();
            loadA(aPre, c + 1);
        }
        copyLoad(c, 0);          // loads covered by computeH(...,0)
        computeH(st, 0);
        copyStore();
        copyLoad(c, 1);          // loads covered by computeH(...,1)
        computeH(st, 1);
        copyStore();
        if (c < 7) {
            storeA(aPre, st ^ 1);
            cp_wait0();
        }
        __syncthreads();
    }

    // ---- tail copy rows (if rowsPer > 8*rcChunk)
    for (int rl = 8 * rcChunk + cRowT; rl < rowsPer; rl += 16) {
        int rg = rows0 + rl;
        if (rg < Nfull) {
            bool cp = (rl < 512) ? (maskS[rl] == 0) : (g_mask[rg] == 0);
            if (cp) {
                size_t base = ((size_t)rg << 6) + cColT;
#pragma unroll
                for (int i = 0; i < 4; ++i)
                    __stcs(&out4[base + i * 16], __ldcs(&in4[base + i * 16]));
            }
        }
    }

    // ---- epilogue: bias add + scatter (streaming stores)
    {
        const int r0 = lid >> 2;
        const int nc = (lid & 3) * 2;
#pragma unroll
        for (int mt = 0; mt < 2; ++mt) {
#pragma unroll
            for (int half = 0; half < 2; ++half) {
                int row = warpM + mt * 16 + r0 + half * 8;   // 0..63
                int mg  = tileM + row;
                if (mg < Mrows) {
                    float* orow = out + (size_t)rowidx[row] * DIM + warpN;
#pragma unroll
                    for (int nt = 0; nt < 8; ++nt) {
                        float2 bv = *(const float2*)&biasS[warpN + nt * 8 + nc];
                        float2 v;
                        v.x = acc[mt][nt][half * 2 + 0] + bv.x;
                        v.y = acc[mt][nt][half * 2 + 1] + bv.y;
                        __stcs((float2*)(orow + nt * 8 + nc), v);
                    }
                }
            }
        }
    }
}

// ---------------- launch ----------------
extern "C" void kernel_launch(void* const* d_in, const int* in_sizes, int n_in,
                              void* d_out, int out_size) {
    const float* h_full = (const float*)d_in[0];
    const float* h_sub  = (const float*)d_in[1];
    const float* W1     = (const float*)d_in[2];
    const float* b1     = (const float*)d_in[3];
    const float* W2     = (const float*)d_in[4];
    const float* b2     = (const float*)d_in[5];
    const void*  idx    = d_in[6];
    float*       out    = (float*)d_out;

    const int dim   = in_sizes[3];
    const int Mrows = in_sizes[1] / dim;
    const int Nfull = in_sizes[0] / dim;

    static cudaStream_t sPrep = nullptr;
    static cudaEvent_t  evFork = nullptr, evMask = nullptr;
    if (!sPrep) {
        cudaStreamCreateWithFlags(&sPrep, cudaStreamNonBlocking);
        cudaEventCreateWithFlags(&evFork, cudaEventDisableTiming);
        cudaEventCreateWithFlags(&evMask, cudaEventDisableTiming);
    }

    cudaFuncSetAttribute(merge_gemm_fp16,
                         cudaFuncAttributeMaxDynamicSharedMemorySize, SM_TOTAL);

    // ---- fork side stream FROM stream 0 (capture-legal), prep in parallel
    cudaEventRecord(evFork, 0);
    cudaStreamWaitEvent(sPrep, evFork, 0);

    const int maskWords = (Nfull + 15) / 16;
    clear_mask<<<(maskWords + 255) / 256, 256, 0, sPrep>>>(
        maskWords, idx, Mrows, (long long)Nfull);
    set_mask<<<(Mrows + 255) / 256, 256, 0, sPrep>>>(idx, Mrows);
    cudaEventRecord(evMask, sPrep);

    convert_W<<<(256 * 512 + 255) / 256, 256>>>(W1, W2);
    cudaStreamWaitEvent(0, evMask, 0);

    // ---- fused GEMM + copy ----
    const int tiles   = (Mrows + BM - 1) / BM;
    const int rowsPer = (Nfull + tiles - 1) / tiles;
    merge_gemm_fp16<<<tiles, THREADS, SM_TOTAL>>>(h_full, h_sub, b1, b2, idx,
                                                  out, Mrows, Nfull, rowsPer);
}

// round 16
// speedup vs baseline: 1.2007x; 1.0275x over previous
#include <cuda_runtime.h>
#include <cuda_fp16.h>
#include <cstdint>

// ---------------------------------------------------------------------------
// NodeUnpool via fp16 HMMA (m16n8k16.f16, fp32 accumulate), single product,
// bulk row-copy interleaved into the GEMM CTA (R12 configuration, best known):
//   out = h_full;  out[idx] = h_full[idx]@W1^T + b1 + h_sub@W2^T + b2
// C[M,256] = [h_full[idx] | h_sub] @ [W1 | W2]^T   (K = 512 concat)
//
// R16 = R12 exact (BM128/BN256/512thr, copy loads AFTER the A-gather in the
// LSU queue -- R14 proved hoisting them costs ~100us) + idx-dtype detection
// folded into clear_mask (one fewer serialized prep launch).
// ---------------------------------------------------------------------------

#define DIM      256
#define BM       128
#define BN       256
#define KC       64
#define THREADS  512
#define ROWB     144            // 64 halves = 128B + 16B pad (conflict-free)

// smem layout (bytes)
#define SM_ROWIDX 0             // int[128]
#define SM_BIAS   512           // float[256]
#define SM_MASK   1536          // uchar[1024] copy-slice masks
#define A_STAGE   (128 * ROWB)  // 18432
#define B_STAGE   (256 * ROWB)  // 36864
#define SM_A      2560          // 2 stages
#define SM_B      (SM_A + 2 * A_STAGE)      // 39424
#define SM_TOTAL  (SM_B + 2 * B_STAGE)      // 113152

#define MASK_CAP  (2u << 20)

__device__ int g_idx_is64;
__device__ __align__(16) __half g_Bw[256 * 512];          // [n][kcat] fp16
__device__ __align__(16) unsigned char g_mask[MASK_CAP];  // 1 = pooled row

// ---------------- helpers ----------------
__device__ __forceinline__ uint32_t smem_u32(const void* p) {
    uint32_t a;
    asm("{ .reg .u64 t; cvta.to.shared.u64 t, %1; cvt.u32.u64 %0, t; }"
        : "=r"(a) : "l"(p));
    return a;
}
__device__ __forceinline__ void cp_async16(uint32_t dst, const void* src) {
    asm volatile("cp.async.cg.shared.global [%0], [%1], 16;"
                 :: "r"(dst), "l"(src) : "memory");
}
__device__ __forceinline__ void cp_commit() {
    asm volatile("cp.async.commit_group;" ::: "memory");
}
__device__ __forceinline__ void cp_wait0() {
    asm volatile("cp.async.wait_group 0;" ::: "memory");
}
__device__ __forceinline__ void ldsm4(uint32_t* r, uint32_t addr) {
    asm volatile("ldmatrix.sync.aligned.m8n8.x4.shared.b16 {%0,%1,%2,%3}, [%4];"
                 : "=r"(r[0]), "=r"(r[1]), "=r"(r[2]), "=r"(r[3]) : "r"(addr));
}
__device__ __forceinline__ uint32_t lds32(uint32_t addr) {
    uint32_t v;
    asm volatile("ld.shared.b32 %0, [%1];" : "=r"(v) : "r"(addr));
    return v;
}
__device__ __forceinline__ void hmma(float* d, const uint32_t* a,
                                     uint32_t b0, uint32_t b1) {
    asm volatile(
        "mma.sync.aligned.m16n8k16.row.col.f32.f16.f16.f32 "
        "{%0,%1,%2,%3}, {%4,%5,%6,%7}, {%8,%9}, {%0,%1,%2,%3};"
        : "+f"(d[0]), "+f"(d[1]), "+f"(d[2]), "+f"(d[3])
        : "r"(a[0]), "r"(a[1]), "r"(a[2]), "r"(a[3]), "r"(b0), "r"(b1));
}

// ---------------- idx dtype ----------------
__device__ __forceinline__ long long load_idx(const void* idx, int r, int is64) {
    if (is64) return reinterpret_cast<const long long*>(idx)[r];
    return (long long)reinterpret_cast<const int*>(idx)[r];
}

// ---------------- mask clear (+ inline dtype detection) ----------------
__global__ void clear_mask(int nWords, const void* idx, int Mrows,
                           long long Nfull) {
    int t = blockIdx.x * blockDim.x + threadIdx.x;
    uint4* p = reinterpret_cast<uint4*>(g_mask);
    if (t < nWords) p[t] = make_uint4(0, 0, 0, 0);
    if (t == 0) {
        const long long* p64 = reinterpret_cast<const long long*>(idx);
        int n = Mrows / 2;
        if (n > 8) n = 8;
        bool ok64 = (n > 0);
        for (int i = 0; i < n; ++i) {
            long long v = p64[i];
            if (v < 0 || v >= Nfull) { ok64 = false; break; }
        }
        g_idx_is64 = ok64 ? 1 : 0;
    }
}
__global__ void set_mask(const void* __restrict__ idx, int Mrows) {
    int t = blockIdx.x * blockDim.x + threadIdx.x;
    if (t < Mrows) {
        long long g = load_idx(idx, t, g_idx_is64);
        g_mask[g] = 1;
    }
}

// ---------------- W -> fp16, [n][kcat] ----------------
__global__ void convert_W(const float* __restrict__ W1, const float* __restrict__ W2) {
    int t = blockIdx.x * blockDim.x + threadIdx.x;   // 256*512
    if (t >= 256 * 512) return;
    int n    = t >> 9;
    int kcat = t & 511;
    float x = (kcat < DIM) ? W1[n * DIM + kcat] : W2[n * DIM + (kcat - DIM)];
    g_Bw[t] = __float2half_rn(x);
}

// ---------------- fused GEMM + interleaved masked copy ----------------
__global__ __launch_bounds__(THREADS, 1)
void merge_gemm_fp16(const float* __restrict__ h_full,
                     const float* __restrict__ h_sub,
                     const float* __restrict__ b1,
                     const float* __restrict__ b2,
                     const void*  __restrict__ idx,
                     float* __restrict__ out,
                     int Mrows, int Nfull, int rowsPer)
{
    extern __shared__ __align__(16) char smem[];
    const uint32_t sbase = smem_u32(smem);

    const int tid   = threadIdx.x;
    const int wid   = tid >> 5;
    const int lid   = tid & 31;
    const int tileM = blockIdx.x * BM;
    const int warpM = (wid & 3) * 32;      // 4 warps in M
    const int warpN = (wid >> 2) * 64;     // 4 warp groups in N

    int*           rowidx = (int*)(smem + SM_ROWIDX);
    float*         biasS  = (float*)(smem + SM_BIAS);
    unsigned char* maskS  = (unsigned char*)(smem + SM_MASK);

    // ---- copy slice for this CTA
    const int rows0   = blockIdx.x * rowsPer;
    const int rcChunk = min(64, (rowsPer + 7) / 8);   // rows per K-chunk
    const int halfR   = (rcChunk + 1) / 2;            // rows per group (<=32)

    const int is64 = g_idx_is64;
    if (tid < BM) {
        int m = tileM + tid;
        rowidx[tid] = (m < Mrows) ? (int)load_idx(idx, m, is64) : 0;
    }
    if (tid < DIM) biasS[tid] = b1[tid] + b2[tid];
    // stage copy-slice masks (<=1024 rows)
    {
        int rl = tid;                                  // 0..511
        int r0 = rows0 + rl;
        maskS[rl] = (rl < rowsPer && r0 < Nfull) ? g_mask[r0] : 1;
        rl += THREADS;
        r0 += THREADS;
        if (rl < 1024) maskS[rl] = (rl < rowsPer && r0 < Nfull) ? g_mask[r0] : 1;
    }
    __syncthreads();

    // ---- B stage fill via cp.async: 256 rows x 128B -> 2048 x 16B segs
    auto issueB = [&](int c, int st) {
        uint32_t dbase = sbase + SM_B + st * B_STAGE;
#pragma unroll
        for (int j = 0; j < 4; ++j) {
            int id  = tid + j * THREADS;     // 0..2047
            int row = id >> 3;               // 0..255
            int seg = id & 7;                // 16B segment
            uint32_t dst = dbase + row * ROWB + seg * 16;
            const char* src = (const char*)g_Bw
                            + (((size_t)row << 9) + c * KC + seg * 8) * 2;
            cp_async16(dst, src);
        }
    };

    // ---- A chunk gather into regs: 2048 float4, 4 per thread
    auto loadA = [&](float4* dst, int c) {
        const bool fromFull = (c < 4);
        const int  kb = (c & 3) * KC;
#pragma unroll
        for (int j = 0; j < 4; ++j) {
            int id = tid + j * THREADS;      // 0..2047
            int r  = id >> 4;                // 0..127
            int c4 = (id & 15) << 2;         // 0..60
            const float* src;
            if (fromFull) {
                src = h_full + (size_t)rowidx[r] * DIM;
            } else {
                int m = tileM + r;
                if (m >= Mrows) m = Mrows - 1;
                src = h_sub + (size_t)m * DIM;
            }
            dst[j] = __ldcs((const float4*)(src + kb + c4));
        }
    };

    // ---- A regs -> fp16 smem (stage st)
    auto storeA = [&](const float4* v, int st) {
        uint32_t abase = (uint32_t)(SM_A + st * A_STAGE);
#pragma unroll
        for (int j = 0; j < 4; ++j) {
            int id = tid + j * THREADS;
            int r  = id >> 4;
            int c4 = (id & 15) << 2;
            float4 q = v[j];
            __half2 p01 = __floats2half2_rn(q.x, q.y);
            __half2 p23 = __floats2half2_rn(q.z, q.w);
            *(uint2*)(smem + abase + r * ROWB + c4 * 2) =
                make_uint2(*(uint32_t*)&p01, *(uint32_t*)&p23);
        }
    };

    float acc[2][8][4];
#pragma unroll
    for (int mt = 0; mt < 2; ++mt)
#pragma unroll
        for (int nt = 0; nt < 8; ++nt)
#pragma unroll
            for (int q = 0; q < 4; ++q) acc[mt][nt][q] = 0.f;

    // ---- compute HALF a KC chunk (kk pair) from stage st
    auto computeH = [&](int st, int kh) {
        const uint32_t aB = sbase + SM_A + st * A_STAGE;
        const uint32_t bB = sbase + SM_B + st * B_STAGE;
#pragma unroll
        for (int kk = kh * 2; kk < kh * 2 + 2; ++kk) {
            uint32_t a[2][4];
#pragma unroll
            for (int mt = 0; mt < 2; ++mt) {
                uint32_t ra = (uint32_t)(warpM + mt * 16 + (lid & 15)) * ROWB
                            + (kk * 16 + (lid >> 4) * 8) * 2;
                ldsm4(a[mt], aB + ra);
            }
#pragma unroll
            for (int nt = 0; nt < 8; ++nt) {
                uint32_t rb = bB + (uint32_t)(warpN + nt * 8 + (lid >> 2)) * ROWB
                            + (kk * 16 + (lid & 3) * 2) * 2;
                uint32_t b0 = lds32(rb), b1v = lds32(rb + 16);
#pragma unroll
                for (int mt = 0; mt < 2; ++mt)
                    hmma(acc[mt][nt], a[mt], b0, b1v);
            }
        }
    };

    // ---- interleaved copy machinery: 1 row / thread-group-of-16 per group
    const float4* in4  = reinterpret_cast<const float4*>(h_full);
    float4*       out4 = reinterpret_cast<float4*>(out);
    const int cRowT = tid >> 4;          // 0..31
    const int cColT = tid & 15;          // f4 lane: cols cColT + i*16

    float4 cb[4];
    int  cRowG  = -1;
    bool cActive = false;

    auto copyLoad = [&](int c, int g) {
        int rl = c * rcChunk + g * halfR + cRowT;       // local row
        int rg = rows0 + rl;
        cActive = (cRowT < halfR) && (rl < rowsPer) && (rg < Nfull)
                  && (maskS[rl] == 0);
        cRowG = rg;
        if (cActive) {
            size_t base = ((size_t)rg << 6) + cColT;
#pragma unroll
            for (int i = 0; i < 4; ++i)
                cb[i] = __ldcs(&in4[base + i * 16]);
        }
    };
    auto copyStore = [&]() {
        if (cActive) {
            size_t base = ((size_t)cRowG << 6) + cColT;
#pragma unroll
            for (int i = 0; i < 4; ++i)
                __stcs(&out4[base + i * 16], cb[i]);
        }
    };

    // ---- prologue: chunk 0 into stage 0
    float4 aPre[4];
    issueB(0, 0);
    cp_commit();
    loadA(aPre, 0);
    storeA(aPre, 0);
    cp_wait0();
    __syncthreads();

    // ---- main loop: GEMM chunks with interleaved copy groups (R12 order)
#pragma unroll 1
    for (int c = 0; c < 8; ++c) {
        const int st = c & 1;
        if (c < 7) {
            issueB(c + 1, st ^ 1);
            cp_commit();
            loadA(aPre, c + 1);
        }
        copyLoad(c, 0);          // loads covered by computeH(...,0)
        computeH(st, 0);
        copyStore();
        copyLoad(c, 1);          // loads covered by computeH(...,1)
        computeH(st, 1);
        copyStore();
        if (c < 7) {
            storeA(aPre, st ^ 1);
            cp_wait0();
        }
        __syncthreads();
    }

    // ---- tail copy rows (if rowsPer > 8*rcChunk; none for default shape)
    for (int rl = 8 * rcChunk + cRowT; rl < rowsPer; rl += 32) {
        int rg = rows0 + rl;
        if (rg < Nfull) {
            bool cp = (rl < 1024) ? (maskS[rl] == 0) : (g_mask[rg] == 0);
            if (cp) {
                size_t base = ((size_t)rg << 6) + cColT;
#pragma unroll
                for (int i = 0; i < 4; ++i)
                    __stcs(&out4[base + i * 16], __ldcs(&in4[base + i * 16]));
            }
        }
    }

    // ---- epilogue: bias add + scatter (streaming stores)
    {
        const int r0 = lid >> 2;
        const int nc = (lid & 3) * 2;
#pragma unroll
        for (int mt = 0; mt < 2; ++mt) {
#pragma unroll
            for (int half = 0; half < 2; ++half) {
                int row = warpM + mt * 16 + r0 + half * 8;
                int mg  = tileM + row;
                if (mg < Mrows) {
                    float* orow = out + (size_t)rowidx[row] * DIM + warpN;
#pragma unroll
                    for (int nt = 0; nt < 8; ++nt) {
                        float2 bv = *(const float2*)&biasS[warpN + nt * 8 + nc];
                        float2 v;
                        v.x = acc[mt][nt][half * 2 + 0] + bv.x;
                        v.y = acc[mt][nt][half * 2 + 1] + bv.y;
                        __stcs((float2*)(orow + nt * 8 + nc), v);
                    }
                }
            }
        }
    }
}

// ---------------- launch ----------------
extern "C" void kernel_launch(void* const* d_in, const int* in_sizes, int n_in,
                              void* d_out, int out_size) {
    const float* h_full = (const float*)d_in[0];
    const float* h_sub  = (const float*)d_in[1];
    const float* W1     = (const float*)d_in[2];
    const float* b1     = (const float*)d_in[3];
    const float* W2     = (const float*)d_in[4];
    const float* b2     = (const float*)d_in[5];
    const void*  idx    = d_in[6];
    float*       out    = (float*)d_out;

    const int dim   = in_sizes[3];
    const int Mrows = in_sizes[1] / dim;
    const int Nfull = in_sizes[0] / dim;

    static cudaStream_t sPrep = nullptr;
    static cudaEvent_t  evFork = nullptr, evMask = nullptr;
    if (!sPrep) {
        cudaStreamCreateWithFlags(&sPrep, cudaStreamNonBlocking);
        cudaEventCreateWithFlags(&evFork, cudaEventDisableTiming);
        cudaEventCreateWithFlags(&evMask, cudaEventDisableTiming);
    }

    cudaFuncSetAttribute(merge_gemm_fp16,
                         cudaFuncAttributeMaxDynamicSharedMemorySize, SM_TOTAL);

    // ---- fork side stream FROM stream 0 (capture-legal), prep in parallel
    cudaEventRecord(evFork, 0);
    cudaStreamWaitEvent(sPrep, evFork, 0);

    const int maskWords = (Nfull + 15) / 16;
    clear_mask<<<(maskWords + 255) / 256, 256, 0, sPrep>>>(
        maskWords, idx, Mrows, (long long)Nfull);
    set_mask<<<(Mrows + 255) / 256, 256, 0, sPrep>>>(idx, Mrows);
    cudaEventRecord(evMask, sPrep);

    convert_W<<<(256 * 512 + 255) / 256, 256>>>(W1, W2);
    cudaStreamWaitEvent(0, evMask, 0);

    // ---- fused GEMM + copy ----
    const int tiles   = (Mrows + BM - 1) / BM;
    const int rowsPer = (Nfull + tiles - 1) / tiles;
    merge_gemm_fp16<<<tiles, THREADS, SM_TOTAL>>>(h_full, h_sub, b1, b2, idx,
                                                  out, Mrows, Nfull, rowsPer);
}

// round 17
// speedup vs baseline: 1.2322x; 1.0262x over previous
#include <cuda_runtime.h>
#include <cuda_fp16.h>
#include <cstdint>

// ---------------------------------------------------------------------------
// NodeUnpool via fp16 HMMA (m16n8k16.f16, fp32 accumulate), single product,
// bulk row-copy interleaved into the GEMM CTA (R12 config):
//   out = h_full;  out[idx] = h_full[idx]@W1^T + b1 + h_sub@W2^T + b2
// C[M,256] = [h_full[idx] | h_sub] @ [W1 | W2]^T   (K = 512 concat)
//
// R17 = R16 + B operand fetched via ldmatrix.x4 (2 nt tiles per instruction)
// instead of 16 scalar lds32 per kk -- cuts B shared-load instructions 4x
// (profile showed L1 47% / issue 20%: LSU-issue bound between barriers).
// ---------------------------------------------------------------------------

#define DIM      256
#define BM       128
#define BN       256
#define KC       64
#define THREADS  512
#define ROWB     144            // 64 halves = 128B + 16B pad (conflict-free)

// smem layout (bytes)
#define SM_ROWIDX 0             // int[128]
#define SM_BIAS   512           // float[256]
#define SM_MASK   1536          // uchar[1024] copy-slice masks
#define A_STAGE   (128 * ROWB)  // 18432
#define B_STAGE   (256 * ROWB)  // 36864
#define SM_A      2560          // 2 stages
#define SM_B      (SM_A + 2 * A_STAGE)      // 39424
#define SM_TOTAL  (SM_B + 2 * B_STAGE)      // 113152

#define MASK_CAP  (2u << 20)

__device__ int g_idx_is64;
__device__ __align__(16) __half g_Bw[256 * 512];          // [n][kcat] fp16
__device__ __align__(16) unsigned char g_mask[MASK_CAP];  // 1 = pooled row

// ---------------- helpers ----------------
__device__ __forceinline__ uint32_t smem_u32(const void* p) {
    uint32_t a;
    asm("{ .reg .u64 t; cvta.to.shared.u64 t, %1; cvt.u32.u64 %0, t; }"
        : "=r"(a) : "l"(p));
    return a;
}
__device__ __forceinline__ void cp_async16(uint32_t dst, const void* src) {
    asm volatile("cp.async.cg.shared.global [%0], [%1], 16;"
                 :: "r"(dst), "l"(src) : "memory");
}
__device__ __forceinline__ void cp_commit() {
    asm volatile("cp.async.commit_group;" ::: "memory");
}
__device__ __forceinline__ void cp_wait0() {
    asm volatile("cp.async.wait_group 0;" ::: "memory");
}
__device__ __forceinline__ void ldsm4(uint32_t* r, uint32_t addr) {
    asm volatile("ldmatrix.sync.aligned.m8n8.x4.shared.b16 {%0,%1,%2,%3}, [%4];"
                 : "=r"(r[0]), "=r"(r[1]), "=r"(r[2]), "=r"(r[3]) : "r"(addr));
}
__device__ __forceinline__ void hmma(float* d, const uint32_t* a,
                                     uint32_t b0, uint32_t b1) {
    asm volatile(
        "mma.sync.aligned.m16n8k16.row.col.f32.f16.f16.f32 "
        "{%0,%1,%2,%3}, {%4,%5,%6,%7}, {%8,%9}, {%0,%1,%2,%3};"
        : "+f"(d[0]), "+f"(d[1]), "+f"(d[2]), "+f"(d[3])
        : "r"(a[0]), "r"(a[1]), "r"(a[2]), "r"(a[3]), "r"(b0), "r"(b1));
}

// ---------------- idx dtype ----------------
__device__ __forceinline__ long long load_idx(const void* idx, int r, int is64) {
    if (is64) return reinterpret_cast<const long long*>(idx)[r];
    return (long long)reinterpret_cast<const int*>(idx)[r];
}

// ---------------- mask clear (+ inline dtype detection) ----------------
__global__ void clear_mask(int nWords, const void* idx, int Mrows,
                           long long Nfull) {
    int t = blockIdx.x * blockDim.x + threadIdx.x;
    uint4* p = reinterpret_cast<uint4*>(g_mask);
    if (t < nWords) p[t] = make_uint4(0, 0, 0, 0);
    if (t == 0) {
        const long long* p64 = reinterpret_cast<const long long*>(idx);
        int n = Mrows / 2;
        if (n > 8) n = 8;
        bool ok64 = (n > 0);
        for (int i = 0; i < n; ++i) {
            long long v = p64[i];
            if (v < 0 || v >= Nfull) { ok64 = false; break; }
        }
        g_idx_is64 = ok64 ? 1 : 0;
    }
}
__global__ void set_mask(const void* __restrict__ idx, int Mrows) {
    int t = blockIdx.x * blockDim.x + threadIdx.x;
    if (t < Mrows) {
        long long g = load_idx(idx, t, g_idx_is64);
        g_mask[g] = 1;
    }
}

// ---------------- W -> fp16, [n][kcat] ----------------
__global__ void convert_W(const float* __restrict__ W1, const float* __restrict__ W2) {
    int t = blockIdx.x * blockDim.x + threadIdx.x;   // 256*512
    if (t >= 256 * 512) return;
    int n    = t >> 9;
    int kcat = t & 511;
    float x = (kcat < DIM) ? W1[n * DIM + kcat] : W2[n * DIM + (kcat - DIM)];
    g_Bw[t] = __float2half_rn(x);
}

// ---------------- fused GEMM + interleaved masked copy ----------------
__global__ __launch_bounds__(THREADS, 1)
void merge_gemm_fp16(const float* __restrict__ h_full,
                     const float* __restrict__ h_sub,
                     const float* __restrict__ b1,
                     const float* __restrict__ b2,
                     const void*  __restrict__ idx,
                     float* __restrict__ out,
                     int Mrows, int Nfull, int rowsPer)
{
    extern __shared__ __align__(16) char smem[];
    const uint32_t sbase = smem_u32(smem);

    const int tid   = threadIdx.x;
    const int wid   = tid >> 5;
    const int lid   = tid & 31;
    const int tileM = blockIdx.x * BM;
    const int warpM = (wid & 3) * 32;      // 4 warps in M
    const int warpN = (wid >> 2) * 64;     // 4 warp groups in N

    int*           rowidx = (int*)(smem + SM_ROWIDX);
    float*         biasS  = (float*)(smem + SM_BIAS);
    unsigned char* maskS  = (unsigned char*)(smem + SM_MASK);

    // ---- copy slice for this CTA
    const int rows0   = blockIdx.x * rowsPer;
    const int rcChunk = min(64, (rowsPer + 7) / 8);   // rows per K-chunk
    const int halfR   = (rcChunk + 1) / 2;            // rows per group (<=32)

    const int is64 = g_idx_is64;
    if (tid < BM) {
        int m = tileM + tid;
        rowidx[tid] = (m < Mrows) ? (int)load_idx(idx, m, is64) : 0;
    }
    if (tid < DIM) biasS[tid] = b1[tid] + b2[tid];
    // stage copy-slice masks (<=1024 rows)
    {
        int rl = tid;                                  // 0..511
        int r0 = rows0 + rl;
        maskS[rl] = (rl < rowsPer && r0 < Nfull) ? g_mask[r0] : 1;
        rl += THREADS;
        r0 += THREADS;
        if (rl < 1024) maskS[rl] = (rl < rowsPer && r0 < Nfull) ? g_mask[r0] : 1;
    }
    __syncthreads();

    // ---- B stage fill via cp.async: 256 rows x 128B -> 2048 x 16B segs
    auto issueB = [&](int c, int st) {
        uint32_t dbase = sbase + SM_B + st * B_STAGE;
#pragma unroll
        for (int j = 0; j < 4; ++j) {
            int id  = tid + j * THREADS;     // 0..2047
            int row = id >> 3;               // 0..255
            int seg = id & 7;                // 16B segment
            uint32_t dst = dbase + row * ROWB + seg * 16;
            const char* src = (const char*)g_Bw
                            + (((size_t)row << 9) + c * KC + seg * 8) * 2;
            cp_async16(dst, src);
        }
    };

    // ---- A chunk gather into regs: 2048 float4, 4 per thread
    auto loadA = [&](float4* dst, int c) {
        const bool fromFull = (c < 4);
        const int  kb = (c & 3) * KC;
#pragma unroll
        for (int j = 0; j < 4; ++j) {
            int id = tid + j * THREADS;      // 0..2047
            int r  = id >> 4;                // 0..127
            int c4 = (id & 15) << 2;         // 0..60
            const float* src;
            if (fromFull) {
                src = h_full + (size_t)rowidx[r] * DIM;
            } else {
                int m = tileM + r;
                if (m >= Mrows) m = Mrows - 1;
                src = h_sub + (size_t)m * DIM;
            }
            dst[j] = __ldcs((const float4*)(src + kb + c4));
        }
    };

    // ---- A regs -> fp16 smem (stage st)
    auto storeA = [&](const float4* v, int st) {
        uint32_t abase = (uint32_t)(SM_A + st * A_STAGE);
#pragma unroll
        for (int j = 0; j < 4; ++j) {
            int id = tid + j * THREADS;
            int r  = id >> 4;
            int c4 = (id & 15) << 2;
            float4 q = v[j];
            __half2 p01 = __floats2half2_rn(q.x, q.y);
            __half2 p23 = __floats2half2_rn(q.z, q.w);
            *(uint2*)(smem + abase + r * ROWB + c4 * 2) =
                make_uint2(*(uint32_t*)&p01, *(uint32_t*)&p23);
        }
    };

    float acc[2][8][4];
#pragma unroll
    for (int mt = 0; mt < 2; ++mt)
#pragma unroll
        for (int nt = 0; nt < 8; ++nt)
#pragma unroll
            for (int q = 0; q < 4; ++q) acc[mt][nt][q] = 0.f;

    // B ldmatrix lane addressing (fixed per thread):
    //   row  = warpN + (lid>=16 ? 8 : 0) + (lid & 7)   [+ p*16 per pair]
    //   koff = ((lid>>3)&1)*16                          [+ kk*32 per step]
    const uint32_t bLaneOff =
        (uint32_t)(warpN + ((lid >> 4) & 1) * 8 + (lid & 7)) * ROWB
        + ((lid >> 3) & 1) * 16;

    // ---- compute HALF a KC chunk (kk pair) from stage st
    auto computeH = [&](int st, int kh) {
        const uint32_t aB = sbase + SM_A + st * A_STAGE;
        const uint32_t bB = sbase + SM_B + st * B_STAGE + bLaneOff;
#pragma unroll
        for (int kk = kh * 2; kk < kh * 2 + 2; ++kk) {
            uint32_t a[2][4];
#pragma unroll
            for (int mt = 0; mt < 2; ++mt) {
                uint32_t ra = (uint32_t)(warpM + mt * 16 + (lid & 15)) * ROWB
                            + (kk * 16 + (lid >> 4) * 8) * 2;
                ldsm4(a[mt], aB + ra);
            }
#pragma unroll
            for (int p = 0; p < 4; ++p) {    // each x4 covers nt = 2p, 2p+1
                uint32_t br[4];
                ldsm4(br, bB + (uint32_t)(p * 16) * ROWB + kk * 32);
#pragma unroll
                for (int mt = 0; mt < 2; ++mt) {
                    hmma(acc[mt][2 * p + 0], a[mt], br[0], br[1]);
                    hmma(acc[mt][2 * p + 1], a[mt], br[2], br[3]);
                }
            }
        }
    };

    // ---- interleaved copy machinery: 1 row / thread-group-of-16 per group
    const float4* in4  = reinterpret_cast<const float4*>(h_full);
    float4*       out4 = reinterpret_cast<float4*>(out);
    const int cRowT = tid >> 4;          // 0..31
    const int cColT = tid & 15;          // f4 lane: cols cColT + i*16

    float4 cb[4];
    int  cRowG  = -1;
    bool cActive = false;

    auto copyLoad = [&](int c, int g) {
        int rl = c * rcChunk + g * halfR + cRowT;       // local row
        int rg = rows0 + rl;
        cActive = (cRowT < halfR) && (rl < rowsPer) && (rg < Nfull)
                  && (maskS[rl] == 0);
        cRowG = rg;
        if (cActive) {
            size_t base = ((size_t)rg << 6) + cColT;
#pragma unroll
            for (int i = 0; i < 4; ++i)
                cb[i] = __ldcs(&in4[base + i * 16]);
        }
    };
    auto copyStore = [&]() {
        if (cActive) {
            size_t base = ((size_t)cRowG << 6) + cColT;
#pragma unroll
            for (int i = 0; i < 4; ++i)
                __stcs(&out4[base + i * 16], cb[i]);
        }
    };

    // ---- prologue: chunk 0 into stage 0
    float4 aPre[4];
    issueB(0, 0);
    cp_commit();
    loadA(aPre, 0);
    storeA(aPre, 0);
    cp_wait0();
    __syncthreads();

    // ---- main loop: GEMM chunks with interleaved copy groups (R12 order)
#pragma unroll 1
    for (int c = 0; c < 8; ++c) {
        const int st = c & 1;
        if (c < 7) {
            issueB(c + 1, st ^ 1);
            cp_commit();
            loadA(aPre, c + 1);
        }
        copyLoad(c, 0);          // loads covered by computeH(...,0)
        computeH(st, 0);
        copyStore();
        copyLoad(c, 1);          // loads covered by computeH(...,1)
        computeH(st, 1);
        copyStore();
        if (c < 7) {
            storeA(aPre, st ^ 1);
            cp_wait0();
        }
        __syncthreads();
    }

    // ---- tail copy rows (if rowsPer > 8*rcChunk; none for default shape)
    for (int rl = 8 * rcChunk + cRowT; rl < rowsPer; rl += 32) {
        int rg = rows0 + rl;
        if (rg < Nfull) {
            bool cp = (rl < 1024) ? (maskS[rl] == 0) : (g_mask[rg] == 0);
            if (cp) {
                size_t base = ((size_t)rg << 6) + cColT;
#pragma unroll
                for (int i = 0; i < 4; ++i)
                    __stcs(&out4[base + i * 16], __ldcs(&in4[base + i * 16]));
            }
        }
    }

    // ---- epilogue: bias add + scatter (streaming stores)
    {
        const int r0 = lid >> 2;
        const int nc = (lid & 3) * 2;
#pragma unroll
        for (int mt = 0; mt < 2; ++mt) {
#pragma unroll
            for (int half = 0; half < 2; ++half) {
                int row = warpM + mt * 16 + r0 + half * 8;
                int mg  = tileM + row;
                if (mg < Mrows) {
                    float* orow = out + (size_t)rowidx[row] * DIM + warpN;
#pragma unroll
                    for (int nt = 0; nt < 8; ++nt) {
                        float2 bv = *(const float2*)&biasS[warpN + nt * 8 + nc];
                        float2 v;
                        v.x = acc[mt][nt][half * 2 + 0] + bv.x;
                        v.y = acc[mt][nt][half * 2 + 1] + bv.y;
                        __stcs((float2*)(orow + nt * 8 + nc), v);
                    }
                }
            }
        }
    }
}

// ---------------- launch ----------------
extern "C" void kernel_launch(void* const* d_in, const int* in_sizes, int n_in,
                              void* d_out, int out_size) {
    const float* h_full = (const float*)d_in[0];
    const float* h_sub  = (const float*)d_in[1];
    const float* W1     = (const float*)d_in[2];
    const float* b1     = (const float*)d_in[3];
    const float* W2     = (const float*)d_in[4];
    const float* b2     = (const float*)d_in[5];
    const void*  idx    = d_in[6];
    float*       out    = (float*)d_out;

    const int dim   = in_sizes[3];
    const int Mrows = in_sizes[1] / dim;
    const int Nfull = in_sizes[0] / dim;

    static cudaStream_t sPrep = nullptr;
    static cudaEvent_t  evFork = nullptr, evMask = nullptr;
    if (!sPrep) {
        cudaStreamCreateWithFlags(&sPrep, cudaStreamNonBlocking);
        cudaEventCreateWithFlags(&evFork, cudaEventDisableTiming);
        cudaEventCreateWithFlags(&evMask, cudaEventDisableTiming);
    }

    cudaFuncSetAttribute(merge_gemm_fp16,
                         cudaFuncAttributeMaxDynamicSharedMemorySize, SM_TOTAL);

    // ---- fork side stream FROM stream 0 (capture-legal), prep in parallel
    cudaEventRecord(evFork, 0);
    cudaStreamWaitEvent(sPrep, evFork, 0);

    const int maskWords = (Nfull + 15) / 16;
    clear_mask<<<(maskWords + 255) / 256, 256, 0, sPrep>>>(
        maskWords, idx, Mrows, (long long)Nfull);
    set_mask<<<(Mrows + 255) / 256, 256, 0, sPrep>>>(idx, Mrows);
    cudaEventRecord(evMask, sPrep);

    convert_W<<<(256 * 512 + 255) / 256, 256>>>(W1, W2);
    cudaStreamWaitEvent(0, evMask, 0);

    // ---- fused GEMM + copy ----
    const int tiles   = (Mrows + BM - 1) / BM;
    const int rowsPer = (Nfull + tiles - 1) / tiles;
    merge_gemm_fp16<<<tiles, THREADS, SM_TOTAL>>>(h_full, h_sub, b1, b2, idx,
                                                  out, Mrows, Nfull, rowsPer);
}